// round 1
// baseline (speedup 1.0000x reference)
#include <cuda_runtime.h>
#include <cuda_bf16.h>

// Problem constants
#define B   16
#define CIN 64
#define COUT 64
#define HH  256
#define WW  256
#define KS  3
#define EPSF 1e-8f

// Scratch for demodulated per-sample weights: [b][cout][cin][9]
__device__ float g_w1[B * COUT * CIN * KS * KS];

// ---------------------------------------------------------------------------
// f32x2 packed-FMA helpers (FFMA2 is PTX-only on sm_103a)
// ---------------------------------------------------------------------------
__device__ __forceinline__ unsigned long long pk2(float lo, float hi) {
    unsigned long long r;
    asm("mov.b64 %0, {%1,%2};" : "=l"(r) : "f"(lo), "f"(hi));
    return r;
}
__device__ __forceinline__ void upk2(unsigned long long v, float& lo, float& hi) {
    asm("mov.b64 {%0,%1}, %2;" : "=f"(lo), "=f"(hi) : "l"(v));
}
__device__ __forceinline__ void fma2(unsigned long long& d,
                                     unsigned long long a,
                                     unsigned long long b) {
    asm("fma.rn.f32x2 %0, %1, %2, %0;" : "+l"(d) : "l"(a), "l"(b));
}

// ---------------------------------------------------------------------------
// Kernel 1: modulate + demodulate weights.
// grid (COUT, B), block (CIN=64). Each thread owns one ci (9 taps).
// ---------------------------------------------------------------------------
__global__ void modw_kernel(const float* __restrict__ w,
                            const float* __restrict__ y,
                            float* __restrict__ w1) {
    const int co = blockIdx.x;
    const int b  = blockIdx.y;
    const int ci = threadIdx.x;

    const float c  = 1.0f / 24.0f;                // (cin*k*k)^-0.5 = 1/sqrt(576)
    const float yv = y[b * CIN + ci] * c;

    float v[9];
    float s = 0.0f;
    const float* wp = w + (co * CIN + ci) * 9;
#pragma unroll
    for (int t = 0; t < 9; t++) {
        v[t] = wp[t] * yv;
        s += v[t] * v[t];
    }
    // reduce over 64 threads (2 warps)
#pragma unroll
    for (int off = 16; off > 0; off >>= 1)
        s += __shfl_down_sync(0xffffffffu, s, off);
    __shared__ float ps[2];
    if ((ci & 31) == 0) ps[ci >> 5] = s;
    __syncthreads();
    const float tot = ps[0] + ps[1];
    const float d = rsqrtf(tot + EPSF);

    float* op = w1 + ((b * COUT + co) * CIN + ci) * 9;
#pragma unroll
    for (int t = 0; t < 9; t++) op[t] = v[t] * d;
}

// ---------------------------------------------------------------------------
// Kernel 2: direct conv, f32x2 packed FMA.
// Block (16,16) = 256 threads. Output tile: 128 wide x 16 tall x 4 couts.
// Each thread: 4 couts x 8 consecutive-in-w pixels (4 f32x2 pairs / cout).
// grid: x = WW/128 = 2, y = HH/16 = 16, z = B * (COUT/4) = 256
// ---------------------------------------------------------------------------
#define TILE_W 128
#define TILE_H 16
#define COG    4
#define XS_W   130            // 128 + 2 halo
#define XS_ST  132            // padded (even -> b64-aligned rows)

__global__ void __launch_bounds__(256, 2)
conv_mod_kernel(const float* __restrict__ X,
                const float* __restrict__ w1,
                float* __restrict__ out) {
    __shared__ __align__(16) float xs[18 * XS_ST];        // input tile + halo
    __shared__ float ws[COG * CIN * 9];                   // 4 couts, all ci

    const int lx = threadIdx.x;          // 0..15
    const int ly = threadIdx.y;          // 0..15
    const int tid = ly * 16 + lx;

    const int bb     = blockIdx.z >> 4;        // sample
    const int coBase = (blockIdx.z & 15) * COG;
    const int wBase  = blockIdx.x * TILE_W;
    const int hBase  = blockIdx.y * TILE_H;

    // stage weight slab: ws[ci][j][tap]
    {
        const float* wsrc = w1 + ((bb * COUT + coBase) * CIN) * 9;
        for (int m = tid; m < COG * CIN * 9; m += 256) {
            int ci  = m / 36;
            int rem = m - ci * 36;
            int j   = rem / 9;
            int tap = rem - j * 9;
            ws[m] = wsrc[(j * CIN + ci) * 9 + tap];
        }
    }

    unsigned long long acc[COG][4];
#pragma unroll
    for (int j = 0; j < COG; j++)
#pragma unroll
        for (int q = 0; q < 4; q++) acc[j][q] = 0ULL;

    const int xcol0 = lx * 8;            // this thread's leftmost smem col

    for (int ci = 0; ci < CIN; ci++) {
        __syncthreads();   // previous iter consumed (and ws staged, on ci==0)

        // stage X tile (rows hBase-1 .. hBase+16, cols wBase-1 .. wBase+128)
        const float* xsrc = X + (bb * CIN + ci) * (HH * WW);
        for (int i = tid; i < 18 * XS_W; i += 256) {
            int r = i / XS_W;
            int c = i - r * XS_W;
            int gh = hBase - 1 + r;
            int gw = wBase - 1 + c;
            float v = 0.0f;
            if ((unsigned)gh < (unsigned)HH && (unsigned)gw < (unsigned)WW)
                v = xsrc[gh * WW + gw];
            xs[r * XS_ST + c] = v;
        }
        __syncthreads();

        const float* wr = ws + ci * 36;

#pragma unroll
        for (int kh = 0; kh < 3; kh++) {
            // load 10 input values (8 pixels + 2 halo) as 5 aligned b64
            const unsigned long long* rp =
                (const unsigned long long*)(xs + (ly + kh) * XS_ST + xcol0);
            unsigned long long P[9];
            P[0] = rp[0]; P[2] = rp[1]; P[4] = rp[2]; P[6] = rp[3]; P[8] = rp[4];
            float x0, x1, x2, x3, x4, x5, x6, x7, x8, x9;
            upk2(P[0], x0, x1);
            upk2(P[2], x2, x3);
            upk2(P[4], x4, x5);
            upk2(P[6], x6, x7);
            upk2(P[8], x8, x9);
            P[1] = pk2(x1, x2);
            P[3] = pk2(x3, x4);
            P[5] = pk2(x5, x6);
            P[7] = pk2(x7, x8);

#pragma unroll
            for (int j = 0; j < COG; j++) {
#pragma unroll
                for (int kw = 0; kw < 3; kw++) {
                    float wv = wr[j * 9 + kh * 3 + kw];   // broadcast LDS
                    unsigned long long w2 = pk2(wv, wv);
                    fma2(acc[j][0], P[kw + 0], w2);
                    fma2(acc[j][1], P[kw + 2], w2);
                    fma2(acc[j][2], P[kw + 4], w2);
                    fma2(acc[j][3], P[kw + 6], w2);
                }
            }
        }
    }

    // epilogue: write 4 couts x 8 pixels
    const int h = hBase + ly;
#pragma unroll
    for (int j = 0; j < COG; j++) {
        float* op = out + ((bb * COUT + coBase + j) * HH + h) * WW + wBase + xcol0;
#pragma unroll
        for (int q = 0; q < 4; q++) {
            float f0, f1;
            upk2(acc[j][q], f0, f1);
            *reinterpret_cast<float2*>(op + 2 * q) = make_float2(f0, f1);
        }
    }
}

// ---------------------------------------------------------------------------
extern "C" void kernel_launch(void* const* d_in, const int* in_sizes, int n_in,
                              void* d_out, int out_size) {
    const float* X = (const float*)d_in[0];      // (16,64,256,256)
    const float* y = (const float*)d_in[1];      // (16,64)
    const float* w = (const float*)d_in[2];      // (64,64,3,3)
    float* out = (float*)d_out;                  // (16,64,256,256)

    float* w1;
    cudaGetSymbolAddress((void**)&w1, g_w1);

    modw_kernel<<<dim3(COUT, B), 64>>>(w, y, w1);

    dim3 grid(WW / TILE_W, HH / TILE_H, B * (COUT / COG));
    dim3 block(16, 16);
    conv_mod_kernel<<<grid, block>>>(X, w1, out);
}

// round 3
// speedup vs baseline: 5.3924x; 5.3924x over previous
#include <cuda_runtime.h>
#include <cstdint>

#define B_    16
#define CIN_  64
#define COUT_ 64
#define HH    256
#define WW    256
#define HW    (HH * WW)
#define EPSF  1e-8f

// Demodulated weights, tf32-rounded, pre-swizzled into the mma-B smem layout:
// [b][tap][kk 0..7][co 0..63][8: ci pairs interleaved (c,c+4)]
__device__ __align__(16) float g_wt[B_ * 9 * 8 * 64 * 8];

__device__ __forceinline__ float f2tf32f(float x) {
    uint32_t r;
    asm("cvt.rna.tf32.f32 %0, %1;" : "=r"(r) : "f"(x));
    return __uint_as_float(r);
}

// m16n8k8 tf32 mma (sm_80+, no arch-accel features needed)
#define MMA_OP(d, a, bv)                                                      \
    asm volatile(                                                             \
        "mma.sync.aligned.m16n8k8.row.col.f32.tf32.tf32.f32 "                 \
        "{%0,%1,%2,%3},{%4,%5,%6,%7},{%8,%9},{%0,%1,%2,%3};"                  \
        : "+f"((d)[0]), "+f"((d)[1]), "+f"((d)[2]), "+f"((d)[3])              \
        : "r"((a)[0]), "r"((a)[1]), "r"((a)[2]), "r"((a)[3]),                 \
          "r"((bv).x), "r"((bv).y))

// ---------------------------------------------------------------------------
// Kernel 1: modulate + demodulate + tf32-round + swizzle into mma-B layout
// grid (COUT, B), block CIN.
// ---------------------------------------------------------------------------
__global__ void modw_kernel(const float* __restrict__ w,
                            const float* __restrict__ y,
                            float* __restrict__ wt) {
    const int co = blockIdx.x;
    const int b  = blockIdx.y;
    const int ci = threadIdx.x;

    const float c  = 1.0f / 24.0f;               // (64*9)^-0.5
    const float yv = y[b * CIN_ + ci] * c;

    float v[9];
    float s = 0.0f;
    const float* wp = w + (co * CIN_ + ci) * 9;
#pragma unroll
    for (int t = 0; t < 9; t++) {
        v[t] = wp[t] * yv;
        s += v[t] * v[t];
    }
#pragma unroll
    for (int off = 16; off > 0; off >>= 1)
        s += __shfl_down_sync(0xffffffffu, s, off);
    __shared__ float ps[2];
    if ((ci & 31) == 0) ps[ci >> 5] = s;
    __syncthreads();
    const float d = rsqrtf(ps[0] + ps[1] + EPSF);

    const int kk  = ci >> 3;
    const int cc  = ci & 7;
    const int sub = (cc < 4) ? (cc * 2) : ((cc - 4) * 2 + 1);
#pragma unroll
    for (int t = 0; t < 9; t++) {
        const size_t idx = ((((size_t)(b * 9 + t) * 8 + kk) * 64 + co) * 8) + sub;
        wt[idx] = f2tf32f(v[t] * d);
    }
}

// ---------------------------------------------------------------------------
// Kernel 2: tf32 mma.sync implicit-GEMM conv.
// CTA: 128 px (2h x 64w) x 64 co. 8 warps: (wid&3) -> px group, (wid>>2) -> co half.
// X tile staged once with halo: xs[64 ci][4 r][66 w], plane stride 264 words.
// Weights double-buffered per tap (16 KB each).
// ---------------------------------------------------------------------------
#define XS_WORDS (64 * 264)        // 16896 words = 67.6 KB
#define WS_WORDS 4096              // 16 KB per tap buffer
#define DYN_SMEM ((XS_WORDS + 2 * WS_WORDS) * 4)

__global__ void __launch_bounds__(256, 2)
conv_mma_kernel(const float* __restrict__ X,
                const float* __restrict__ wt,
                float* __restrict__ out) {
    extern __shared__ __align__(16) float smem[];
    float* xs = smem;

    const int tid  = threadIdx.x;
    const int lane = tid & 31;
    const int wid  = tid >> 5;

    const int b  = blockIdx.z;
    const int h0 = blockIdx.y * 2;
    const int w0 = blockIdx.x * 64;

    const int px0 = (wid & 3) * 32;      // warp pixel base (0..96)
    const int co0 = (wid >> 2) * 32;     // warp cout base (0 or 32)

    // ---- stage X tile (once, covers all 9 taps), tf32-rounded ----
    {
        const float* Xb = X + (size_t)b * CIN_ * HW;
        for (int idx = tid; idx < XS_WORDS; idx += 256) {
            const int row66 = idx / 66;          // = ci*4 + r
            const int c     = idx - row66 * 66;
            const int ci    = row66 >> 2;
            const int r     = row66 & 3;
            const int gh    = h0 - 1 + r;
            const int gw    = w0 - 1 + c;
            float v = 0.0f;
            if ((unsigned)gh < (unsigned)HH && (unsigned)gw < (unsigned)WW)
                v = Xb[(size_t)ci * HW + gh * WW + gw];
            xs[idx] = f2tf32f(v);
        }
    }
    // ---- stage weights for tap 0 into buffer 0 ----
    {
        const float4* src = (const float4*)(wt + (size_t)(b * 9) * 4096);
        float4* dst = (float4*)(smem + XS_WORDS);
#pragma unroll
        for (int j = 0; j < 4; j++) dst[j * 256 + tid] = src[j * 256 + tid];
    }
    __syncthreads();

    float acc[2][4][4];
#pragma unroll
    for (int mt = 0; mt < 2; mt++)
#pragma unroll
        for (int nt = 0; nt < 4; nt++)
#pragma unroll
            for (int q = 0; q < 4; q++) acc[mt][nt][q] = 0.0f;

    for (int t = 0; t < 9; t++) {
        // prefetch next tap's weights into the other buffer
        if (t < 8) {
            const float4* src = (const float4*)(wt + (size_t)(b * 9 + t + 1) * 4096);
            float4* dst = (float4*)(smem + XS_WORDS + ((t + 1) & 1) * WS_WORDS);
#pragma unroll
            for (int j = 0; j < 4; j++) dst[j * 256 + tid] = src[j * 256 + tid];
        }

        const int kh = t / 3, kw = t - kh * 3;
        // A base: +ci(lane&3)*264 +row((px0>>6)+kh)*66 +col((px0&63)+(lane>>2)+kw)
        const float* abase = xs + (size_t)(lane & 3) * 264
                           + ((px0 >> 6) + kh) * 66
                           + (px0 & 63) + (lane >> 2) + kw;
        // B base (uint2 units): kk*256 + co*4 + (lane&3)
        const uint2* bbase = (const uint2*)(smem + XS_WORDS + (t & 1) * WS_WORDS)
                           + (size_t)(co0 + (lane >> 2)) * 4 + (lane & 3);

#pragma unroll
        for (int kk = 0; kk < 8; kk++) {
            const float* ap = abase + kk * (8 * 264);
            uint32_t a0[4], a1[4];
            a0[0] = __float_as_uint(ap[0]);
            a0[1] = __float_as_uint(ap[8]);
            a0[2] = __float_as_uint(ap[1056]);
            a0[3] = __float_as_uint(ap[1064]);
            a1[0] = __float_as_uint(ap[16]);
            a1[1] = __float_as_uint(ap[24]);
            a1[2] = __float_as_uint(ap[1072]);
            a1[3] = __float_as_uint(ap[1080]);

            const uint2* bp = bbase + kk * 256;
            uint2 bb0 = bp[0];
            uint2 bb1 = bp[32];
            uint2 bb2 = bp[64];
            uint2 bb3 = bp[96];

            MMA_OP(acc[0][0], a0, bb0);
            MMA_OP(acc[1][0], a1, bb0);
            MMA_OP(acc[0][1], a0, bb1);
            MMA_OP(acc[1][1], a1, bb1);
            MMA_OP(acc[0][2], a0, bb2);
            MMA_OP(acc[1][2], a1, bb2);
            MMA_OP(acc[0][3], a0, bb3);
            MMA_OP(acc[1][3], a1, bb3);
        }
        __syncthreads();   // protect weight buffer reuse (2-deep rotation)
    }

    // ---- epilogue: scatter accumulators ----
#pragma unroll
    for (int mt = 0; mt < 2; mt++) {
        const int pxm  = px0 + mt * 16 + (lane >> 2);
        const int h    = h0 + (pxm >> 6);
        const int wcol = w0 + (pxm & 63);
        float* o0 = out + (size_t)b * COUT_ * HW + (size_t)h * WW + wcol;
#pragma unroll
        for (int nt = 0; nt < 4; nt++) {
            const int co = co0 + nt * 8 + 2 * (lane & 3);
            float* p = o0 + (size_t)co * HW;
            p[0]      = acc[mt][nt][0];   // (px, co)
            p[HW]     = acc[mt][nt][1];   // (px, co+1)
            p[8]      = acc[mt][nt][2];   // (px+8, co)
            p[HW + 8] = acc[mt][nt][3];   // (px+8, co+1)
        }
    }
}

// ---------------------------------------------------------------------------
extern "C" void kernel_launch(void* const* d_in, const int* in_sizes, int n_in,
                              void* d_out, int out_size) {
    const float* X = (const float*)d_in[0];      // (16,64,256,256)
    const float* y = (const float*)d_in[1];      // (16,64)
    const float* w = (const float*)d_in[2];      // (64,64,3,3)
    float* out = (float*)d_out;                  // (16,64,256,256)

    float* wt;
    cudaGetSymbolAddress((void**)&wt, g_wt);

    cudaFuncSetAttribute(conv_mma_kernel,
                         cudaFuncAttributeMaxDynamicSharedMemorySize, DYN_SMEM);

    modw_kernel<<<dim3(COUT_, B_), CIN_>>>(w, y, wt);

    dim3 grid(WW / 64, HH / 2, B_);
    conv_mma_kernel<<<grid, 256, DYN_SMEM>>>(X, wt, out);
}